// round 1
// baseline (speedup 1.0000x reference)
#include <cuda_runtime.h>
#include <math.h>

// Problem constants (fixed by the reference)
#define Bc   2
#define Sc   2048
#define Ec   1024
#define Hc   16
#define Dc   64
#define NTOK (Bc*Sc)          // 4096 rows
#define ATT_SCALE 0.125f      // 1/sqrt(64)

// Scratch (static __device__ — no allocation allowed)
__device__ float g_q  [Bc*Sc*Ec];
__device__ float g_k  [Bc*Sc*Ec];
__device__ float g_v  [Bc*Sc*Ec];
__device__ float g_ctx[Bc*Sc*Ec];

// ---------------------------------------------------------------------------
// GEMM: C[M,N] = A[M,K] @ W[N,K]^T   (torch Linear convention, W is [out,in])
// 64x64 block tile, 16-wide K panel, 256 threads, 4x4 micro-tile per thread.
// Smem staged transposed (As[k][r], Ws[k][c]) so operand fetch is LDS.128.
// ---------------------------------------------------------------------------
template<int M, int N, int K>
__global__ void __launch_bounds__(256) gemm_xwT(const float* __restrict__ A,
                                                const float* __restrict__ W,
                                                float* __restrict__ C) {
    __shared__ float As[16][68];   // [k][r], pad->stride 68 (mult of 4 for f4 align)
    __shared__ float Ws[16][68];   // [k][c]

    const int tid = threadIdx.x;
    const int tx  = tid & 15;      // 0..15  -> n micro
    const int ty  = tid >> 4;      // 0..15  -> m micro
    const int m0  = blockIdx.y * 64;
    const int n0  = blockIdx.x * 64;

    const int lk = tid & 15;       // k index for loads
    const int lr = tid >> 4;       // base row 0..15

    float acc[4][4];
    #pragma unroll
    for (int i = 0; i < 4; i++)
        #pragma unroll
        for (int j = 0; j < 4; j++) acc[i][j] = 0.f;

    for (int kk = 0; kk < K; kk += 16) {
        __syncthreads();
        #pragma unroll
        for (int it = 0; it < 4; it++) {
            const int r = lr + it * 16;
            As[lk][r] = A[(size_t)(m0 + r) * K + kk + lk];
            Ws[lk][r] = W[(size_t)(n0 + r) * K + kk + lk];
        }
        __syncthreads();

        #pragma unroll
        for (int k = 0; k < 16; k++) {
            const float4 a4 = *(const float4*)&As[k][ty * 4];
            const float4 b4 = *(const float4*)&Ws[k][tx * 4];
            const float ar[4] = {a4.x, a4.y, a4.z, a4.w};
            const float br[4] = {b4.x, b4.y, b4.z, b4.w};
            #pragma unroll
            for (int i = 0; i < 4; i++)
                #pragma unroll
                for (int j = 0; j < 4; j++)
                    acc[i][j] = fmaf(ar[i], br[j], acc[i][j]);
        }
    }

    #pragma unroll
    for (int i = 0; i < 4; i++) {
        float4 o4 = make_float4(acc[i][0], acc[i][1], acc[i][2], acc[i][3]);
        *(float4*)&C[(size_t)(m0 + ty * 4 + i) * N + n0 + tx * 4] = o4;
    }
}

// ---------------------------------------------------------------------------
// Flash attention, causal, fp32. One block = one (b, h, 64-row q-tile).
// Online softmax. Smem: Qs[d][r] (68 stride), K/P shared buffer (68 stride),
// Vs[k][d] (64 stride). 51200 B dynamic smem.
// ---------------------------------------------------------------------------
__global__ void __launch_bounds__(256) flash_attn(const float* __restrict__ Q,
                                                  const float* __restrict__ Kg,
                                                  const float* __restrict__ Vg,
                                                  float* __restrict__ Ctx) {
    extern __shared__ float sm[];
    float* Qs = sm;                 // [64][68]  Qs[d*68 + r]
    float* KP = sm + 64 * 68;       // Ks[d*68+c]  then reused as Ps[r*68+c]
    float* Vs = sm + 2 * 64 * 68;   // [64][64]  Vs[k*64 + d]

    const int tid = threadIdx.x;
    const int tx  = tid & 15;
    const int ty  = tid >> 4;
    const int r0  = ty * 4;         // query rows (within tile)
    const int c0  = tx * 4;         // key cols / head-dim cols (within tile)

    const int qt = blockIdx.x;      // q tile 0..31
    const int h  = blockIdx.y;      // head
    const int b  = blockIdx.z;      // batch
    const size_t base = (size_t)b * Sc * Ec + (size_t)h * Dc;

    // Load Q tile transposed: Qs[d][r]
    for (int idx = tid; idx < 64 * 64; idx += 256) {
        const int r = idx >> 6;
        const int d = idx & 63;
        Qs[d * 68 + r] = Q[base + (size_t)(qt * 64 + r) * Ec + d];
    }

    float m[4], l[4], o[4][4];
    #pragma unroll
    for (int i = 0; i < 4; i++) {
        m[i] = -1e30f; l[i] = 0.f;
        #pragma unroll
        for (int j = 0; j < 4; j++) o[i][j] = 0.f;
    }

    for (int jt = 0; jt <= qt; jt++) {
        __syncthreads();   // protect KP (P reads) & Vs from previous iter / Qs load
        // Load K transposed, V natural
        for (int idx = tid; idx < 64 * 64; idx += 256) {
            const int c = idx >> 6;
            const int d = idx & 63;
            const size_t g = base + (size_t)(jt * 64 + c) * Ec + d;
            KP[d * 68 + c] = Kg[g];
            Vs[c * 64 + d] = Vg[g];
        }
        __syncthreads();

        // S = Q @ K^T
        float s[4][4];
        #pragma unroll
        for (int i = 0; i < 4; i++)
            #pragma unroll
            for (int j = 0; j < 4; j++) s[i][j] = 0.f;

        #pragma unroll 8
        for (int d = 0; d < 64; d++) {
            const float4 a4 = *(const float4*)&Qs[d * 68 + r0];
            const float4 b4 = *(const float4*)&KP[d * 68 + c0];
            const float ar[4] = {a4.x, a4.y, a4.z, a4.w};
            const float br[4] = {b4.x, b4.y, b4.z, b4.w};
            #pragma unroll
            for (int i = 0; i < 4; i++)
                #pragma unroll
                for (int j = 0; j < 4; j++)
                    s[i][j] = fmaf(ar[i], br[j], s[i][j]);
        }

        // scale + causal mask (only on diagonal tile)
        if (jt == qt) {
            #pragma unroll
            for (int i = 0; i < 4; i++)
                #pragma unroll
                for (int j = 0; j < 4; j++)
                    s[i][j] = (c0 + j > r0 + i) ? -1e30f : s[i][j] * ATT_SCALE;
        } else {
            #pragma unroll
            for (int i = 0; i < 4; i++)
                #pragma unroll
                for (int j = 0; j < 4; j++) s[i][j] *= ATT_SCALE;
        }

        __syncthreads();   // all threads done reading KP as K-tile

        // online softmax, write P into KP
        #pragma unroll
        for (int i = 0; i < 4; i++) {
            float mt = fmaxf(fmaxf(s[i][0], s[i][1]), fmaxf(s[i][2], s[i][3]));
            #pragma unroll
            for (int off = 1; off < 16; off <<= 1)
                mt = fmaxf(mt, __shfl_xor_sync(0xffffffffu, mt, off));
            const float mnew = fmaxf(m[i], mt);
            float rs = 0.f;
            #pragma unroll
            for (int j = 0; j < 4; j++) {
                s[i][j] = __expf(s[i][j] - mnew);
                rs += s[i][j];
            }
            #pragma unroll
            for (int off = 1; off < 16; off <<= 1)
                rs += __shfl_xor_sync(0xffffffffu, rs, off);
            const float alpha = __expf(m[i] - mnew);
            l[i] = l[i] * alpha + rs;
            m[i] = mnew;
            #pragma unroll
            for (int j = 0; j < 4; j++) o[i][j] *= alpha;
            *(float4*)&KP[(r0 + i) * 68 + c0] =
                make_float4(s[i][0], s[i][1], s[i][2], s[i][3]);
        }
        __syncthreads();

        // O += P @ V
        #pragma unroll 4
        for (int k = 0; k < 64; k++) {
            const float4 v4 = *(const float4*)&Vs[k * 64 + c0];
            const float vr[4] = {v4.x, v4.y, v4.z, v4.w};
            #pragma unroll
            for (int i = 0; i < 4; i++) {
                const float p = KP[(r0 + i) * 68 + k];
                #pragma unroll
                for (int j = 0; j < 4; j++)
                    o[i][j] = fmaf(p, vr[j], o[i][j]);
            }
        }
    }

    // normalize and write context in [B,S,E] layout (head h at cols h*64..)
    #pragma unroll
    for (int i = 0; i < 4; i++) {
        const float inv = 1.0f / l[i];
        float4 o4 = make_float4(o[i][0] * inv, o[i][1] * inv,
                                o[i][2] * inv, o[i][3] * inv);
        *(float4*)&Ctx[base + (size_t)(qt * 64 + r0 + i) * Ec + c0] = o4;
    }
}

// ---------------------------------------------------------------------------
extern "C" void kernel_launch(void* const* d_in, const int* in_sizes, int n_in,
                              void* d_out, int out_size) {
    (void)in_sizes; (void)n_in; (void)out_size;
    const float* x  = (const float*)d_in[0];
    const float* wq = (const float*)d_in[1];
    const float* wk = (const float*)d_in[2];
    const float* wv = (const float*)d_in[3];
    const float* wo = (const float*)d_in[4];
    float* out = (float*)d_out;

    float *q, *k, *v, *ctx;
    cudaGetSymbolAddress((void**)&q,   g_q);
    cudaGetSymbolAddress((void**)&k,   g_k);
    cudaGetSymbolAddress((void**)&v,   g_v);
    cudaGetSymbolAddress((void**)&ctx, g_ctx);

    const dim3 gblk(256);
    const dim3 ggrd(Ec / 64, NTOK / 64);   // (16, 64)

    gemm_xwT<NTOK, Ec, Ec><<<ggrd, gblk>>>(x, wq, q);
    gemm_xwT<NTOK, Ec, Ec><<<ggrd, gblk>>>(x, wk, k);
    gemm_xwT<NTOK, Ec, Ec><<<ggrd, gblk>>>(x, wv, v);

    const int smem = (2 * 64 * 68 + 64 * 64) * (int)sizeof(float);  // 51200 B
    cudaFuncSetAttribute(flash_attn, cudaFuncAttributeMaxDynamicSharedMemorySize, smem);
    flash_attn<<<dim3(Sc / 64, Hc, Bc), 256, smem>>>(q, k, v, ctx);

    gemm_xwT<NTOK, Ec, Ec><<<ggrd, gblk>>>(ctx, wo, out);
}

// round 3
// speedup vs baseline: 1.3198x; 1.3198x over previous
#include <cuda_runtime.h>
#include <cstdint>
#include <math.h>

// Problem constants
#define Bc   2
#define Sc   2048
#define Ec   1024
#define Hc   16
#define Dc   64
#define NTOK (Bc*Sc)          // 4096
#define ATT_SCALE 0.125f

// Scratch (static __device__ — no allocation allowed)
__device__ float g_q  [Bc*Sc*Ec];
__device__ float g_k  [Bc*Sc*Ec];
__device__ float g_v  [Bc*Sc*Ec];
__device__ float g_ctx[Bc*Sc*Ec];

// ---------------------------------------------------------------------------
// 3xTF32 GEMM via mma.sync (baseline PTX, no 'a'-suffix features needed)
// C[M,N] = A[M,K] @ W[N,K]^T, exact-ish via hi/lo tf32 split:
//   A*W ~= Ahi*Whi + Ahi*Wlo + Alo*Whi   (lo*lo term ~2^-42, dropped)
// 128x128 CTA tile, k-panel 32, 256 threads = 8 warps (2 x 4), warp = 64x32.
// Split computed on the fly while staging k-panels into smem.
// ---------------------------------------------------------------------------
#define GK   Ec
#define KPAN 32
#define PADS 36                 // smem row stride (floats); 36%32=4 -> conflict-free frags

__device__ __forceinline__ float trunc_tf32(float a) {
    return __int_as_float(__float_as_int(a) & 0xFFFFE000);
}

__device__ __forceinline__ void mma_tf32(float* c, const uint32_t* a, const uint32_t* b) {
    asm volatile(
        "mma.sync.aligned.m16n8k8.row.col.f32.tf32.tf32.f32 "
        "{%0,%1,%2,%3}, {%4,%5,%6,%7}, {%8,%9}, {%0,%1,%2,%3};"
        : "+f"(c[0]), "+f"(c[1]), "+f"(c[2]), "+f"(c[3])
        : "r"(a[0]), "r"(a[1]), "r"(a[2]), "r"(a[3]), "r"(b[0]), "r"(b[1]));
}

__global__ void __launch_bounds__(256) gemm3_mma(const float* __restrict__ A,
                                                 const float* __restrict__ W,
                                                 float* __restrict__ C) {
    extern __shared__ float sm[];
    float* Ah = sm;                         // [128][PADS]
    float* Al = Ah + 128 * PADS;
    float* Bh = Al + 128 * PADS;
    float* Bl = Bh + 128 * PADS;

    const int tid  = threadIdx.x;
    const int wid  = tid >> 5;
    const int lane = tid & 31;
    const int wm   = (wid & 1) * 64;        // warp m offset in tile
    const int wn   = (wid >> 1) * 32;       // warp n offset in tile
    const int m0   = blockIdx.y * 128;
    const int n0   = blockIdx.x * 128;

    const int lq = lane >> 2;               // 0..7
    const int lr = lane & 3;                // 0..3

    float acc[4][4][4];
    #pragma unroll
    for (int i = 0; i < 4; i++)
        #pragma unroll
        for (int j = 0; j < 4; j++)
            #pragma unroll
            for (int e = 0; e < 4; e++) acc[i][j][e] = 0.f;

    for (int kk = 0; kk < GK; kk += KPAN) {
        __syncthreads();
        // stage k-panels with on-the-fly hi/lo split
        #pragma unroll
        for (int it = 0; it < 4; it++) {
            const int i  = tid + it * 256;          // 0..1023
            const int r  = i >> 3;
            const int c4 = (i & 7) * 4;
            float4 va = *(const float4*)&A[(size_t)(m0 + r) * GK + kk + c4];
            float4 vb = *(const float4*)&W[(size_t)(n0 + r) * GK + kk + c4];
            float* ah = &Ah[r * PADS + c4];
            float* al = &Al[r * PADS + c4];
            float* bh = &Bh[r * PADS + c4];
            float* bl = &Bl[r * PADS + c4];
            const float av[4] = {va.x, va.y, va.z, va.w};
            const float bv[4] = {vb.x, vb.y, vb.z, vb.w};
            #pragma unroll
            for (int e = 0; e < 4; e++) {
                const float ahv = trunc_tf32(av[e]);
                const float bhv = trunc_tf32(bv[e]);
                ah[e] = ahv; al[e] = trunc_tf32(av[e] - ahv);
                bh[e] = bhv; bl[e] = trunc_tf32(bv[e] - bhv);
            }
        }
        __syncthreads();

        #pragma unroll
        for (int ks = 0; ks < 4; ks++) {
            const int k0 = ks * 8;
            // A fragments (hi & lo) for 4 m-tiles
            uint32_t afh[4][4], afl[4][4];
            #pragma unroll
            for (int mt = 0; mt < 4; mt++) {
                const int rb = wm + mt * 16;
                const int r0 = (rb + lq) * PADS + k0 + lr;
                const int r1 = (rb + lq + 8) * PADS + k0 + lr;
                afh[mt][0] = __float_as_uint(Ah[r0]);
                afh[mt][1] = __float_as_uint(Ah[r1]);
                afh[mt][2] = __float_as_uint(Ah[r0 + 4]);
                afh[mt][3] = __float_as_uint(Ah[r1 + 4]);
                afl[mt][0] = __float_as_uint(Al[r0]);
                afl[mt][1] = __float_as_uint(Al[r1]);
                afl[mt][2] = __float_as_uint(Al[r0 + 4]);
                afl[mt][3] = __float_as_uint(Al[r1 + 4]);
            }
            // B fragments (hi & lo) for 4 n-tiles
            uint32_t bfh[4][2], bfl[4][2];
            #pragma unroll
            for (int nt = 0; nt < 4; nt++) {
                const int cb = (wn + nt * 8 + lq) * PADS + k0 + lr;
                bfh[nt][0] = __float_as_uint(Bh[cb]);
                bfh[nt][1] = __float_as_uint(Bh[cb + 4]);
                bfl[nt][0] = __float_as_uint(Bl[cb]);
                bfl[nt][1] = __float_as_uint(Bl[cb + 4]);
            }
            #pragma unroll
            for (int mt = 0; mt < 4; mt++)
                #pragma unroll
                for (int nt = 0; nt < 4; nt++) {
                    mma_tf32(acc[mt][nt], afh[mt], bfh[nt]);
                    mma_tf32(acc[mt][nt], afh[mt], bfl[nt]);
                    mma_tf32(acc[mt][nt], afl[mt], bfh[nt]);
                }
        }
    }

    // epilogue: c0,c1 at (row lq, col lr*2), c2,c3 at (row lq+8)
    #pragma unroll
    for (int mt = 0; mt < 4; mt++) {
        const int r0 = m0 + wm + mt * 16 + lq;
        #pragma unroll
        for (int nt = 0; nt < 4; nt++) {
            const int cc = n0 + wn + nt * 8 + lr * 2;
            *(float2*)&C[(size_t)r0 * Ec + cc]       = make_float2(acc[mt][nt][0], acc[mt][nt][1]);
            *(float2*)&C[(size_t)(r0 + 8) * Ec + cc] = make_float2(acc[mt][nt][2], acc[mt][nt][3]);
        }
    }
}

// ---------------------------------------------------------------------------
// Flash attention, causal, fp32 (unchanged — known good)
// ---------------------------------------------------------------------------
__global__ void __launch_bounds__(256) flash_attn(const float* __restrict__ Q,
                                                  const float* __restrict__ Kg,
                                                  const float* __restrict__ Vg,
                                                  float* __restrict__ Ctx) {
    extern __shared__ float sm[];
    float* Qs = sm;                 // [64][68]
    float* KP = sm + 64 * 68;       // K tile then P tile
    float* Vs = sm + 2 * 64 * 68;   // [64][64]

    const int tid = threadIdx.x;
    const int tx  = tid & 15;
    const int ty  = tid >> 4;
    const int r0  = ty * 4;
    const int c0  = tx * 4;

    const int qt = blockIdx.x;
    const int h  = blockIdx.y;
    const int b  = blockIdx.z;
    const size_t base = (size_t)b * Sc * Ec + (size_t)h * Dc;

    for (int idx = tid; idx < 64 * 64; idx += 256) {
        const int r = idx >> 6;
        const int d = idx & 63;
        Qs[d * 68 + r] = Q[base + (size_t)(qt * 64 + r) * Ec + d];
    }

    float m[4], l[4], o[4][4];
    #pragma unroll
    for (int i = 0; i < 4; i++) {
        m[i] = -1e30f; l[i] = 0.f;
        #pragma unroll
        for (int j = 0; j < 4; j++) o[i][j] = 0.f;
    }

    for (int jt = 0; jt <= qt; jt++) {
        __syncthreads();
        for (int idx = tid; idx < 64 * 64; idx += 256) {
            const int c = idx >> 6;
            const int d = idx & 63;
            const size_t g = base + (size_t)(jt * 64 + c) * Ec + d;
            KP[d * 68 + c] = Kg[g];
            Vs[c * 64 + d] = Vg[g];
        }
        __syncthreads();

        float s[4][4];
        #pragma unroll
        for (int i = 0; i < 4; i++)
            #pragma unroll
            for (int j = 0; j < 4; j++) s[i][j] = 0.f;

        #pragma unroll 8
        for (int d = 0; d < 64; d++) {
            const float4 a4 = *(const float4*)&Qs[d * 68 + r0];
            const float4 b4 = *(const float4*)&KP[d * 68 + c0];
            const float ar[4] = {a4.x, a4.y, a4.z, a4.w};
            const float br[4] = {b4.x, b4.y, b4.z, b4.w};
            #pragma unroll
            for (int i = 0; i < 4; i++)
                #pragma unroll
                for (int j = 0; j < 4; j++)
                    s[i][j] = fmaf(ar[i], br[j], s[i][j]);
        }

        if (jt == qt) {
            #pragma unroll
            for (int i = 0; i < 4; i++)
                #pragma unroll
                for (int j = 0; j < 4; j++)
                    s[i][j] = (c0 + j > r0 + i) ? -1e30f : s[i][j] * ATT_SCALE;
        } else {
            #pragma unroll
            for (int i = 0; i < 4; i++)
                #pragma unroll
                for (int j = 0; j < 4; j++) s[i][j] *= ATT_SCALE;
        }

        __syncthreads();

        #pragma unroll
        for (int i = 0; i < 4; i++) {
            float mt = fmaxf(fmaxf(s[i][0], s[i][1]), fmaxf(s[i][2], s[i][3]));
            #pragma unroll
            for (int off = 1; off < 16; off <<= 1)
                mt = fmaxf(mt, __shfl_xor_sync(0xffffffffu, mt, off));
            const float mnew = fmaxf(m[i], mt);
            float rs = 0.f;
            #pragma unroll
            for (int j = 0; j < 4; j++) {
                s[i][j] = __expf(s[i][j] - mnew);
                rs += s[i][j];
            }
            #pragma unroll
            for (int off = 1; off < 16; off <<= 1)
                rs += __shfl_xor_sync(0xffffffffu, rs, off);
            const float alpha = __expf(m[i] - mnew);
            l[i] = l[i] * alpha + rs;
            m[i] = mnew;
            #pragma unroll
            for (int j = 0; j < 4; j++) o[i][j] *= alpha;
            *(float4*)&KP[(r0 + i) * 68 + c0] =
                make_float4(s[i][0], s[i][1], s[i][2], s[i][3]);
        }
        __syncthreads();

        #pragma unroll 4
        for (int k = 0; k < 64; k++) {
            const float4 v4 = *(const float4*)&Vs[k * 64 + c0];
            const float vr[4] = {v4.x, v4.y, v4.z, v4.w};
            #pragma unroll
            for (int i = 0; i < 4; i++) {
                const float p = KP[(r0 + i) * 68 + k];
                #pragma unroll
                for (int j = 0; j < 4; j++)
                    o[i][j] = fmaf(p, vr[j], o[i][j]);
            }
        }
    }

    #pragma unroll
    for (int i = 0; i < 4; i++) {
        const float inv = 1.0f / l[i];
        float4 o4 = make_float4(o[i][0] * inv, o[i][1] * inv,
                                o[i][2] * inv, o[i][3] * inv);
        *(float4*)&Ctx[base + (size_t)(qt * 64 + r0 + i) * Ec + c0] = o4;
    }
}

// ---------------------------------------------------------------------------
extern "C" void kernel_launch(void* const* d_in, const int* in_sizes, int n_in,
                              void* d_out, int out_size) {
    (void)in_sizes; (void)n_in; (void)out_size;
    const float* x  = (const float*)d_in[0];
    const float* wq = (const float*)d_in[1];
    const float* wk = (const float*)d_in[2];
    const float* wv = (const float*)d_in[3];
    const float* wo = (const float*)d_in[4];
    float* out = (float*)d_out;

    float *q, *k, *v, *ctx;
    cudaGetSymbolAddress((void**)&q,   g_q);
    cudaGetSymbolAddress((void**)&k,   g_k);
    cudaGetSymbolAddress((void**)&v,   g_v);
    cudaGetSymbolAddress((void**)&ctx, g_ctx);

    const int gsmem = 4 * 128 * PADS * (int)sizeof(float);   // 73728 B
    cudaFuncSetAttribute(gemm3_mma, cudaFuncAttributeMaxDynamicSharedMemorySize, gsmem);
    const dim3 ggrd(Ec / 128, NTOK / 128);   // (8, 32)

    gemm3_mma<<<ggrd, 256, gsmem>>>(x, wq, q);
    gemm3_mma<<<ggrd, 256, gsmem>>>(x, wk, k);
    gemm3_mma<<<ggrd, 256, gsmem>>>(x, wv, v);

    const int asmem = (2 * 64 * 68 + 64 * 64) * (int)sizeof(float);
    cudaFuncSetAttribute(flash_attn, cudaFuncAttributeMaxDynamicSharedMemorySize, asmem);
    flash_attn<<<dim3(Sc / 64, Hc, Bc), 256, asmem>>>(q, k, v, ctx);

    gemm3_mma<<<ggrd, 256, gsmem>>>(ctx, wo, out);
}

// round 4
// speedup vs baseline: 1.5092x; 1.1435x over previous
#include <cuda_runtime.h>
#include <cstdint>
#include <math.h>

// Problem constants
#define Bc   2
#define Sc   2048
#define Ec   1024
#define Hc   16
#define Dc   64
#define NTOK (Bc*Sc)          // 4096
#define ATT_SCALE 0.125f

// Scratch (static __device__ — no allocation allowed)
__device__ float g_q  [Bc*Sc*Ec];
__device__ float g_k  [Bc*Sc*Ec];
__device__ float g_v  [Bc*Sc*Ec];
__device__ float g_ctx[Bc*Sc*Ec];

__device__ __forceinline__ float trunc_tf32(float a) {
    return __int_as_float(__float_as_int(a) & 0xFFFFE000);
}

__device__ __forceinline__ void mma_tf32(float* c, const uint32_t* a, const uint32_t* b) {
    asm volatile(
        "mma.sync.aligned.m16n8k8.row.col.f32.tf32.tf32.f32 "
        "{%0,%1,%2,%3}, {%4,%5,%6,%7}, {%8,%9}, {%0,%1,%2,%3};"
        : "+f"(c[0]), "+f"(c[1]), "+f"(c[2]), "+f"(c[3])
        : "r"(a[0]), "r"(a[1]), "r"(a[2]), "r"(a[3]), "r"(b[0]), "r"(b[1]));
}

// ---------------------------------------------------------------------------
// 3xTF32 GEMM via mma.sync  (unchanged from R3 — known good)
// ---------------------------------------------------------------------------
#define GK   Ec
#define KPAN 32
#define PADS 36

__global__ void __launch_bounds__(256) gemm3_mma(const float* __restrict__ A,
                                                 const float* __restrict__ W,
                                                 float* __restrict__ C) {
    extern __shared__ float sm[];
    float* Ah = sm;
    float* Al = Ah + 128 * PADS;
    float* Bh = Al + 128 * PADS;
    float* Bl = Bh + 128 * PADS;

    const int tid  = threadIdx.x;
    const int wid  = tid >> 5;
    const int lane = tid & 31;
    const int wm   = (wid & 1) * 64;
    const int wn   = (wid >> 1) * 32;
    const int m0   = blockIdx.y * 128;
    const int n0   = blockIdx.x * 128;

    const int lq = lane >> 2;
    const int lr = lane & 3;

    float acc[4][4][4];
    #pragma unroll
    for (int i = 0; i < 4; i++)
        #pragma unroll
        for (int j = 0; j < 4; j++)
            #pragma unroll
            for (int e = 0; e < 4; e++) acc[i][j][e] = 0.f;

    for (int kk = 0; kk < GK; kk += KPAN) {
        __syncthreads();
        #pragma unroll
        for (int it = 0; it < 4; it++) {
            const int i  = tid + it * 256;
            const int r  = i >> 3;
            const int c4 = (i & 7) * 4;
            float4 va = *(const float4*)&A[(size_t)(m0 + r) * GK + kk + c4];
            float4 vb = *(const float4*)&W[(size_t)(n0 + r) * GK + kk + c4];
            float* ah = &Ah[r * PADS + c4];
            float* al = &Al[r * PADS + c4];
            float* bh = &Bh[r * PADS + c4];
            float* bl = &Bl[r * PADS + c4];
            const float av[4] = {va.x, va.y, va.z, va.w};
            const float bv[4] = {vb.x, vb.y, vb.z, vb.w};
            #pragma unroll
            for (int e = 0; e < 4; e++) {
                const float ahv = trunc_tf32(av[e]);
                const float bhv = trunc_tf32(bv[e]);
                ah[e] = ahv; al[e] = trunc_tf32(av[e] - ahv);
                bh[e] = bhv; bl[e] = trunc_tf32(bv[e] - bhv);
            }
        }
        __syncthreads();

        #pragma unroll
        for (int ks = 0; ks < 4; ks++) {
            const int k0 = ks * 8;
            uint32_t afh[4][4], afl[4][4];
            #pragma unroll
            for (int mt = 0; mt < 4; mt++) {
                const int rb = wm + mt * 16;
                const int r0 = (rb + lq) * PADS + k0 + lr;
                const int r1 = (rb + lq + 8) * PADS + k0 + lr;
                afh[mt][0] = __float_as_uint(Ah[r0]);
                afh[mt][1] = __float_as_uint(Ah[r1]);
                afh[mt][2] = __float_as_uint(Ah[r0 + 4]);
                afh[mt][3] = __float_as_uint(Ah[r1 + 4]);
                afl[mt][0] = __float_as_uint(Al[r0]);
                afl[mt][1] = __float_as_uint(Al[r1]);
                afl[mt][2] = __float_as_uint(Al[r0 + 4]);
                afl[mt][3] = __float_as_uint(Al[r1 + 4]);
            }
            uint32_t bfh[4][2], bfl[4][2];
            #pragma unroll
            for (int nt = 0; nt < 4; nt++) {
                const int cb = (wn + nt * 8 + lq) * PADS + k0 + lr;
                bfh[nt][0] = __float_as_uint(Bh[cb]);
                bfh[nt][1] = __float_as_uint(Bh[cb + 4]);
                bfl[nt][0] = __float_as_uint(Bl[cb]);
                bfl[nt][1] = __float_as_uint(Bl[cb + 4]);
            }
            #pragma unroll
            for (int mt = 0; mt < 4; mt++)
                #pragma unroll
                for (int nt = 0; nt < 4; nt++) {
                    mma_tf32(acc[mt][nt], afh[mt], bfh[nt]);
                    mma_tf32(acc[mt][nt], afh[mt], bfl[nt]);
                    mma_tf32(acc[mt][nt], afl[mt], bfh[nt]);
                }
        }
    }

    #pragma unroll
    for (int mt = 0; mt < 4; mt++) {
        const int r0 = m0 + wm + mt * 16 + lq;
        #pragma unroll
        for (int nt = 0; nt < 4; nt++) {
            const int cc = n0 + wn + nt * 8 + lr * 2;
            *(float2*)&C[(size_t)r0 * Ec + cc]       = make_float2(acc[mt][nt][0], acc[mt][nt][1]);
            *(float2*)&C[(size_t)(r0 + 8) * Ec + cc] = make_float2(acc[mt][nt][2], acc[mt][nt][3]);
        }
    }
}

// ---------------------------------------------------------------------------
// Flash attention, causal, tensor cores via 3xTF32 mma.sync.
// CTA = 64 q-rows, kv tiles of 64. 4 warps, warp = 16 rows x 64 cols.
// Smem: Qh/Ql [64][68], Kh/Kl [64][68] (reused for P hi/lo), Vth/Vtl [64][68]
// (V stored transposed [dim][key]).  104448 B -> 2 CTAs/SM.
// ---------------------------------------------------------------------------
#define FST 68
#define SQH 0
#define SQL (64*FST)
#define SKH (2*64*FST)
#define SKL (3*64*FST)
#define SVH (4*64*FST)
#define SVL (5*64*FST)
#define FA_SMEM (6*64*FST*4)   // 104448 B

__global__ void __launch_bounds__(128) flash_attn_mma(const float* __restrict__ Q,
                                                      const float* __restrict__ Kg,
                                                      const float* __restrict__ Vg,
                                                      float* __restrict__ Ctx) {
    extern __shared__ float sm[];
    float* Qh  = sm + SQH;
    float* Ql  = sm + SQL;
    float* Kh  = sm + SKH;   // K tile hi, later P hi
    float* Kl  = sm + SKL;   // K tile lo, later P lo
    float* Vth = sm + SVH;   // V^T hi [dim][key]
    float* Vtl = sm + SVL;

    const int tid  = threadIdx.x;
    const int wid  = tid >> 5;
    const int lane = tid & 31;
    const int lq   = lane >> 2;
    const int lr   = lane & 3;
    const int wrow = wid * 16;

    const int qt = gridDim.x - 1 - blockIdx.x;   // long CTAs first
    const int h  = blockIdx.y;
    const int b  = blockIdx.z;
    const size_t base = (size_t)b * Sc * Ec + (size_t)h * Dc;

    // stage Q tile hi/lo: [64 rows][64 dims]
    #pragma unroll
    for (int it = 0; it < 8; it++) {
        const int i  = tid + it * 128;
        const int r  = i >> 4;
        const int d0 = (i & 15) * 4;
        float4 v = *(const float4*)&Q[base + (size_t)(qt * 64 + r) * Ec + d0];
        float4 hv, lv;
        hv.x = trunc_tf32(v.x); lv.x = trunc_tf32(v.x - hv.x);
        hv.y = trunc_tf32(v.y); lv.y = trunc_tf32(v.y - hv.y);
        hv.z = trunc_tf32(v.z); lv.z = trunc_tf32(v.z - hv.z);
        hv.w = trunc_tf32(v.w); lv.w = trunc_tf32(v.w - hv.w);
        *(float4*)&Qh[r * FST + d0] = hv;
        *(float4*)&Ql[r * FST + d0] = lv;
    }

    float o[8][4];
    #pragma unroll
    for (int nt = 0; nt < 8; nt++)
        #pragma unroll
        for (int e = 0; e < 4; e++) o[nt][e] = 0.f;
    float mr0 = -1e30f, mr1 = -1e30f, lr0 = 0.f, lr1 = 0.f;

    for (int jt = 0; jt <= qt; jt++) {
        __syncthreads();  // previous iter done with Kh/Kl (P) and Vt
        // stage K hi/lo and V^T hi/lo
        #pragma unroll
        for (int it = 0; it < 8; it++) {
            const int i  = tid + it * 128;
            const int r  = i >> 4;            // key index
            const int d0 = (i & 15) * 4;      // dim base
            const size_t g = base + (size_t)(jt * 64 + r) * Ec + d0;
            float4 kv = *(const float4*)&Kg[g];
            float4 vv = *(const float4*)&Vg[g];
            float4 khv, klv;
            khv.x = trunc_tf32(kv.x); klv.x = trunc_tf32(kv.x - khv.x);
            khv.y = trunc_tf32(kv.y); klv.y = trunc_tf32(kv.y - khv.y);
            khv.z = trunc_tf32(kv.z); klv.z = trunc_tf32(kv.z - khv.z);
            khv.w = trunc_tf32(kv.w); klv.w = trunc_tf32(kv.w - khv.w);
            *(float4*)&Kh[r * FST + d0] = khv;
            *(float4*)&Kl[r * FST + d0] = klv;
            const float va[4] = {vv.x, vv.y, vv.z, vv.w};
            #pragma unroll
            for (int e = 0; e < 4; e++) {
                const float hv = trunc_tf32(va[e]);
                Vth[(d0 + e) * FST + r] = hv;
                Vtl[(d0 + e) * FST + r] = trunc_tf32(va[e] - hv);
            }
        }
        __syncthreads();

        // S = Q @ K^T (3xTF32)
        float s[8][4];
        #pragma unroll
        for (int nt = 0; nt < 8; nt++)
            #pragma unroll
            for (int e = 0; e < 4; e++) s[nt][e] = 0.f;

        #pragma unroll
        for (int ks = 0; ks < 8; ks++) {
            const int k0 = ks * 8;
            const int r0 = (wrow + lq) * FST + k0 + lr;
            const int r1 = (wrow + lq + 8) * FST + k0 + lr;
            uint32_t ah[4], al[4];
            ah[0] = __float_as_uint(Qh[r0]);     ah[1] = __float_as_uint(Qh[r1]);
            ah[2] = __float_as_uint(Qh[r0 + 4]); ah[3] = __float_as_uint(Qh[r1 + 4]);
            al[0] = __float_as_uint(Ql[r0]);     al[1] = __float_as_uint(Ql[r1]);
            al[2] = __float_as_uint(Ql[r0 + 4]); al[3] = __float_as_uint(Ql[r1 + 4]);
            #pragma unroll
            for (int nt = 0; nt < 8; nt++) {
                const int cb = (nt * 8 + lq) * FST + k0 + lr;
                uint32_t bh[2], bl[2];
                bh[0] = __float_as_uint(Kh[cb]); bh[1] = __float_as_uint(Kh[cb + 4]);
                bl[0] = __float_as_uint(Kl[cb]); bl[1] = __float_as_uint(Kl[cb + 4]);
                mma_tf32(s[nt], ah, bh);
                mma_tf32(s[nt], ah, bl);
                mma_tf32(s[nt], al, bh);
            }
        }

        // scale + causal mask on diagonal tile
        if (jt == qt) {
            const int row0 = wrow + lq, row1 = wrow + lq + 8;
            #pragma unroll
            for (int nt = 0; nt < 8; nt++) {
                const int c0 = nt * 8 + lr * 2;
                s[nt][0] = (c0     > row0) ? -1e30f : s[nt][0] * ATT_SCALE;
                s[nt][1] = (c0 + 1 > row0) ? -1e30f : s[nt][1] * ATT_SCALE;
                s[nt][2] = (c0     > row1) ? -1e30f : s[nt][2] * ATT_SCALE;
                s[nt][3] = (c0 + 1 > row1) ? -1e30f : s[nt][3] * ATT_SCALE;
            }
        } else {
            #pragma unroll
            for (int nt = 0; nt < 8; nt++)
                #pragma unroll
                for (int e = 0; e < 4; e++) s[nt][e] *= ATT_SCALE;
        }

        // online softmax (rows lq, lq+8; reduce over lanes sharing lq)
        float mt0 = -1e30f, mt1 = -1e30f;
        #pragma unroll
        for (int nt = 0; nt < 8; nt++) {
            mt0 = fmaxf(mt0, fmaxf(s[nt][0], s[nt][1]));
            mt1 = fmaxf(mt1, fmaxf(s[nt][2], s[nt][3]));
        }
        mt0 = fmaxf(mt0, __shfl_xor_sync(0xffffffffu, mt0, 1));
        mt0 = fmaxf(mt0, __shfl_xor_sync(0xffffffffu, mt0, 2));
        mt1 = fmaxf(mt1, __shfl_xor_sync(0xffffffffu, mt1, 1));
        mt1 = fmaxf(mt1, __shfl_xor_sync(0xffffffffu, mt1, 2));
        const float mn0 = fmaxf(mr0, mt0);
        const float mn1 = fmaxf(mr1, mt1);
        const float a0 = __expf(mr0 - mn0);
        const float a1 = __expf(mr1 - mn1);
        float rs0 = 0.f, rs1 = 0.f;
        #pragma unroll
        for (int nt = 0; nt < 8; nt++) {
            s[nt][0] = __expf(s[nt][0] - mn0); rs0 += s[nt][0];
            s[nt][1] = __expf(s[nt][1] - mn0); rs0 += s[nt][1];
            s[nt][2] = __expf(s[nt][2] - mn1); rs1 += s[nt][2];
            s[nt][3] = __expf(s[nt][3] - mn1); rs1 += s[nt][3];
        }
        rs0 += __shfl_xor_sync(0xffffffffu, rs0, 1);
        rs0 += __shfl_xor_sync(0xffffffffu, rs0, 2);
        rs1 += __shfl_xor_sync(0xffffffffu, rs1, 1);
        rs1 += __shfl_xor_sync(0xffffffffu, rs1, 2);
        lr0 = lr0 * a0 + rs0; mr0 = mn0;
        lr1 = lr1 * a1 + rs1; mr1 = mn1;
        #pragma unroll
        for (int nt = 0; nt < 8; nt++) {
            o[nt][0] *= a0; o[nt][1] *= a0;
            o[nt][2] *= a1; o[nt][3] *= a1;
        }

        __syncthreads();  // all warps done reading Kh/Kl as K-tile
        // write P hi/lo into Kh/Kl: P[row][key]
        {
            const int rb0 = (wrow + lq) * FST;
            const int rb1 = (wrow + lq + 8) * FST;
            #pragma unroll
            for (int nt = 0; nt < 8; nt++) {
                const int cc = nt * 8 + lr * 2;
                const float h0 = trunc_tf32(s[nt][0]);
                const float h1 = trunc_tf32(s[nt][1]);
                const float h2 = trunc_tf32(s[nt][2]);
                const float h3 = trunc_tf32(s[nt][3]);
                *(float2*)&Kh[rb0 + cc] = make_float2(h0, h1);
                *(float2*)&Kl[rb0 + cc] = make_float2(trunc_tf32(s[nt][0] - h0),
                                                      trunc_tf32(s[nt][1] - h1));
                *(float2*)&Kh[rb1 + cc] = make_float2(h2, h3);
                *(float2*)&Kl[rb1 + cc] = make_float2(trunc_tf32(s[nt][2] - h2),
                                                      trunc_tf32(s[nt][3] - h3));
            }
        }
        __syncthreads();

        // O += P @ V  (A = P [row][key], B = V^T [dim][key])
        #pragma unroll
        for (int ks = 0; ks < 8; ks++) {
            const int k0 = ks * 8;
            const int r0 = (wrow + lq) * FST + k0 + lr;
            const int r1 = (wrow + lq + 8) * FST + k0 + lr;
            uint32_t ph[4], pl[4];
            ph[0] = __float_as_uint(Kh[r0]);     ph[1] = __float_as_uint(Kh[r1]);
            ph[2] = __float_as_uint(Kh[r0 + 4]); ph[3] = __float_as_uint(Kh[r1 + 4]);
            pl[0] = __float_as_uint(Kl[r0]);     pl[1] = __float_as_uint(Kl[r1]);
            pl[2] = __float_as_uint(Kl[r0 + 4]); pl[3] = __float_as_uint(Kl[r1 + 4]);
            #pragma unroll
            for (int nt = 0; nt < 8; nt++) {
                const int cb = (nt * 8 + lq) * FST + k0 + lr;
                uint32_t bh[2], bl[2];
                bh[0] = __float_as_uint(Vth[cb]); bh[1] = __float_as_uint(Vth[cb + 4]);
                bl[0] = __float_as_uint(Vtl[cb]); bl[1] = __float_as_uint(Vtl[cb + 4]);
                mma_tf32(o[nt], ph, bh);
                mma_tf32(o[nt], ph, bl);
                mma_tf32(o[nt], pl, bh);
            }
        }
    }

    // epilogue: normalize, write context
    const float inv0 = 1.0f / lr0;
    const float inv1 = 1.0f / lr1;
    const size_t ro0 = base + (size_t)(qt * 64 + wrow + lq) * Ec;
    const size_t ro1 = base + (size_t)(qt * 64 + wrow + lq + 8) * Ec;
    #pragma unroll
    for (int nt = 0; nt < 8; nt++) {
        const int cc = nt * 8 + lr * 2;
        *(float2*)&Ctx[ro0 + cc] = make_float2(o[nt][0] * inv0, o[nt][1] * inv0);
        *(float2*)&Ctx[ro1 + cc] = make_float2(o[nt][2] * inv1, o[nt][3] * inv1);
    }
}

// ---------------------------------------------------------------------------
extern "C" void kernel_launch(void* const* d_in, const int* in_sizes, int n_in,
                              void* d_out, int out_size) {
    (void)in_sizes; (void)n_in; (void)out_size;
    const float* x  = (const float*)d_in[0];
    const float* wq = (const float*)d_in[1];
    const float* wk = (const float*)d_in[2];
    const float* wv = (const float*)d_in[3];
    const float* wo = (const float*)d_in[4];
    float* out = (float*)d_out;

    float *q, *k, *v, *ctx;
    cudaGetSymbolAddress((void**)&q,   g_q);
    cudaGetSymbolAddress((void**)&k,   g_k);
    cudaGetSymbolAddress((void**)&v,   g_v);
    cudaGetSymbolAddress((void**)&ctx, g_ctx);

    const int gsmem = 4 * 128 * PADS * (int)sizeof(float);
    cudaFuncSetAttribute(gemm3_mma, cudaFuncAttributeMaxDynamicSharedMemorySize, gsmem);
    const dim3 ggrd(Ec / 128, NTOK / 128);

    gemm3_mma<<<ggrd, 256, gsmem>>>(x, wq, q);
    gemm3_mma<<<ggrd, 256, gsmem>>>(x, wk, k);
    gemm3_mma<<<ggrd, 256, gsmem>>>(x, wv, v);

    cudaFuncSetAttribute(flash_attn_mma, cudaFuncAttributeMaxDynamicSharedMemorySize, FA_SMEM);
    flash_attn_mma<<<dim3(Sc / 64, Hc, Bc), 128, FA_SMEM>>>(q, k, v, ctx);

    gemm3_mma<<<ggrd, 256, gsmem>>>(ctx, wo, out);
}

// round 5
// speedup vs baseline: 1.6338x; 1.0826x over previous
#include <cuda_runtime.h>
#include <cstdint>
#include <math.h>

// Problem constants
#define Bc   2
#define Sc   2048
#define Ec   1024
#define Hc   16
#define Dc   64
#define NTOK (Bc*Sc)          // 4096
#define ATT_SCALE 0.125f

// Scratch (static __device__ — no allocation allowed)
__device__ float g_q  [Bc*Sc*Ec];
__device__ float g_k  [Bc*Sc*Ec];
__device__ float g_v  [Bc*Sc*Ec];
__device__ float g_ctx[Bc*Sc*Ec];

__device__ __forceinline__ float trunc_tf32(float a) {
    return __int_as_float(__float_as_int(a) & 0xFFFFE000);
}

__device__ __forceinline__ void mma_tf32(float* c, const uint32_t* a, const uint32_t* b) {
    asm volatile(
        "mma.sync.aligned.m16n8k8.row.col.f32.tf32.tf32.f32 "
        "{%0,%1,%2,%3}, {%4,%5,%6,%7}, {%8,%9}, {%0,%1,%2,%3};"
        : "+f"(c[0]), "+f"(c[1]), "+f"(c[2]), "+f"(c[3])
        : "r"(a[0]), "r"(a[1]), "r"(a[2]), "r"(a[3]), "r"(b[0]), "r"(b[1]));
}

// split a fp32 into tf32 hi/lo (as uint regs for mma)
__device__ __forceinline__ void split_hl_u(float v, uint32_t& h, uint32_t& l) {
    const float hv = trunc_tf32(v);
    h = __float_as_uint(hv);
    l = __float_as_uint(trunc_tf32(v - hv));
}

// ---------------------------------------------------------------------------
// 3xTF32 GEMM via mma.sync. fp32 staged in smem, hi/lo split at fragment load.
// C[M,N] = A[M,K] @ W[N,K]^T. 128x128 CTA tile, k-panel 32, 256 thr, 8 warps.
// ---------------------------------------------------------------------------
#define GK   Ec
#define KPAN 32
#define PADS 36

__global__ void __launch_bounds__(256, 2) gemm3_mma(const float* __restrict__ A,
                                                    const float* __restrict__ W,
                                                    float* __restrict__ C) {
    extern __shared__ float sm[];
    float* As = sm;                         // [128][PADS] fp32
    float* Bs = As + 128 * PADS;

    const int tid  = threadIdx.x;
    const int wid  = tid >> 5;
    const int lane = tid & 31;
    const int wm   = (wid & 1) * 64;
    const int wn   = (wid >> 1) * 32;
    const int m0   = blockIdx.y * 128;
    const int n0   = blockIdx.x * 128;

    const int lq = lane >> 2;
    const int lr = lane & 3;

    float acc[4][4][4];
    #pragma unroll
    for (int i = 0; i < 4; i++)
        #pragma unroll
        for (int j = 0; j < 4; j++)
            #pragma unroll
            for (int e = 0; e < 4; e++) acc[i][j][e] = 0.f;

    for (int kk = 0; kk < GK; kk += KPAN) {
        __syncthreads();
        #pragma unroll
        for (int it = 0; it < 4; it++) {
            const int i  = tid + it * 256;
            const int r  = i >> 3;
            const int c4 = (i & 7) * 4;
            *(float4*)&As[r * PADS + c4] = *(const float4*)&A[(size_t)(m0 + r) * GK + kk + c4];
            *(float4*)&Bs[r * PADS + c4] = *(const float4*)&W[(size_t)(n0 + r) * GK + kk + c4];
        }
        __syncthreads();

        #pragma unroll
        for (int ks = 0; ks < 4; ks++) {
            const int k0 = ks * 8;
            uint32_t afh[4][4], afl[4][4];
            #pragma unroll
            for (int mt = 0; mt < 4; mt++) {
                const int rb = wm + mt * 16;
                const int r0 = (rb + lq) * PADS + k0 + lr;
                const int r1 = (rb + lq + 8) * PADS + k0 + lr;
                split_hl_u(As[r0],     afh[mt][0], afl[mt][0]);
                split_hl_u(As[r1],     afh[mt][1], afl[mt][1]);
                split_hl_u(As[r0 + 4], afh[mt][2], afl[mt][2]);
                split_hl_u(As[r1 + 4], afh[mt][3], afl[mt][3]);
            }
            #pragma unroll
            for (int nt = 0; nt < 4; nt++) {
                const int cb = (wn + nt * 8 + lq) * PADS + k0 + lr;
                uint32_t bfh[2], bfl[2];
                split_hl_u(Bs[cb],     bfh[0], bfl[0]);
                split_hl_u(Bs[cb + 4], bfh[1], bfl[1]);
                #pragma unroll
                for (int mt = 0; mt < 4; mt++) {
                    mma_tf32(acc[mt][nt], afh[mt], bfh);
                    mma_tf32(acc[mt][nt], afh[mt], bfl);
                    mma_tf32(acc[mt][nt], afl[mt], bfh);
                }
            }
        }
    }

    #pragma unroll
    for (int mt = 0; mt < 4; mt++) {
        const int r0 = m0 + wm + mt * 16 + lq;
        #pragma unroll
        for (int nt = 0; nt < 4; nt++) {
            const int cc = n0 + wn + nt * 8 + lr * 2;
            *(float2*)&C[(size_t)r0 * Ec + cc]       = make_float2(acc[mt][nt][0], acc[mt][nt][1]);
            *(float2*)&C[(size_t)(r0 + 8) * Ec + cc] = make_float2(acc[mt][nt][2], acc[mt][nt][3]);
        }
    }
}

// ---------------------------------------------------------------------------
// Flash attention, causal, 3xTF32 mma.sync.
// fp32 smem (split at fragment load): Qs/Ks/Vts [64][68] = 52224 B -> 4 CTA/SM.
// P is redistributed via warp shuffles (no smem, no extra syncs).
// ---------------------------------------------------------------------------
#define FST 68
#define FA_SMEM (3*64*FST*4)   // 52224 B

__global__ void __launch_bounds__(128, 4) flash_attn_mma(const float* __restrict__ Q,
                                                         const float* __restrict__ Kg,
                                                         const float* __restrict__ Vg,
                                                         float* __restrict__ Ctx) {
    extern __shared__ float sm[];
    float* Qs  = sm;                  // [64][FST] fp32, [row][dim]
    float* Ks  = sm + 64 * FST;       // [row][dim]
    float* Vts = sm + 2 * 64 * FST;   // [dim][key] (transposed)

    const int tid  = threadIdx.x;
    const int wid  = tid >> 5;
    const int lane = tid & 31;
    const int lq   = lane >> 2;
    const int lr   = lane & 3;
    const int wrow = wid * 16;

    const int qt = gridDim.x - 1 - blockIdx.x;   // long CTAs first
    const int h  = blockIdx.y;
    const int b  = blockIdx.z;
    const size_t base = (size_t)b * Sc * Ec + (size_t)h * Dc;

    // stage Q tile fp32
    #pragma unroll
    for (int it = 0; it < 8; it++) {
        const int i  = tid + it * 128;
        const int r  = i >> 4;
        const int d0 = (i & 15) * 4;
        *(float4*)&Qs[r * FST + d0] =
            *(const float4*)&Q[base + (size_t)(qt * 64 + r) * Ec + d0];
    }

    float o[8][4];
    #pragma unroll
    for (int nt = 0; nt < 8; nt++)
        #pragma unroll
        for (int e = 0; e < 4; e++) o[nt][e] = 0.f;
    float mr0 = -1e30f, mr1 = -1e30f, lr0 = 0.f, lr1 = 0.f;

    const unsigned FM = 0xffffffffu;
    const int srcA = (lane & ~3) | (lr >> 1);
    const int srcB = srcA + 2;
    const bool oddc = (lr & 1);

    for (int jt = 0; jt <= qt; jt++) {
        __syncthreads();  // previous iter done reading Ks/Vts
        // stage K (rowwise) and V (transposed), fp32
        #pragma unroll
        for (int it = 0; it < 8; it++) {
            const int i  = tid + it * 128;
            const int r  = i >> 4;
            const int d0 = (i & 15) * 4;
            const size_t g = base + (size_t)(jt * 64 + r) * Ec + d0;
            *(float4*)&Ks[r * FST + d0] = *(const float4*)&Kg[g];
            float4 vv = *(const float4*)&Vg[g];
            Vts[(d0 + 0) * FST + r] = vv.x;
            Vts[(d0 + 1) * FST + r] = vv.y;
            Vts[(d0 + 2) * FST + r] = vv.z;
            Vts[(d0 + 3) * FST + r] = vv.w;
        }
        __syncthreads();

        // S = Q @ K^T (3xTF32, split at fragment load)
        float s[8][4];
        #pragma unroll
        for (int nt = 0; nt < 8; nt++)
            #pragma unroll
            for (int e = 0; e < 4; e++) s[nt][e] = 0.f;

        #pragma unroll
        for (int ks = 0; ks < 8; ks++) {
            const int k0 = ks * 8;
            const int r0 = (wrow + lq) * FST + k0 + lr;
            const int r1 = (wrow + lq + 8) * FST + k0 + lr;
            uint32_t ah[4], al[4];
            split_hl_u(Qs[r0],     ah[0], al[0]);
            split_hl_u(Qs[r1],     ah[1], al[1]);
            split_hl_u(Qs[r0 + 4], ah[2], al[2]);
            split_hl_u(Qs[r1 + 4], ah[3], al[3]);
            #pragma unroll
            for (int nt = 0; nt < 8; nt++) {
                const int cb = (nt * 8 + lq) * FST + k0 + lr;
                uint32_t bh[2], bl[2];
                split_hl_u(Ks[cb],     bh[0], bl[0]);
                split_hl_u(Ks[cb + 4], bh[1], bl[1]);
                mma_tf32(s[nt], ah, bh);
                mma_tf32(s[nt], ah, bl);
                mma_tf32(s[nt], al, bh);
            }
        }

        // scale + causal mask on diagonal tile
        if (jt == qt) {
            const int row0 = wrow + lq, row1 = wrow + lq + 8;
            #pragma unroll
            for (int nt = 0; nt < 8; nt++) {
                const int c0 = nt * 8 + lr * 2;
                s[nt][0] = (c0     > row0) ? -1e30f : s[nt][0] * ATT_SCALE;
                s[nt][1] = (c0 + 1 > row0) ? -1e30f : s[nt][1] * ATT_SCALE;
                s[nt][2] = (c0     > row1) ? -1e30f : s[nt][2] * ATT_SCALE;
                s[nt][3] = (c0 + 1 > row1) ? -1e30f : s[nt][3] * ATT_SCALE;
            }
        } else {
            #pragma unroll
            for (int nt = 0; nt < 8; nt++)
                #pragma unroll
                for (int e = 0; e < 4; e++) s[nt][e] *= ATT_SCALE;
        }

        // online softmax (rows lq, lq+8; reduce across lanes sharing lq)
        float mt0 = -1e30f, mt1 = -1e30f;
        #pragma unroll
        for (int nt = 0; nt < 8; nt++) {
            mt0 = fmaxf(mt0, fmaxf(s[nt][0], s[nt][1]));
            mt1 = fmaxf(mt1, fmaxf(s[nt][2], s[nt][3]));
        }
        mt0 = fmaxf(mt0, __shfl_xor_sync(FM, mt0, 1));
        mt0 = fmaxf(mt0, __shfl_xor_sync(FM, mt0, 2));
        mt1 = fmaxf(mt1, __shfl_xor_sync(FM, mt1, 1));
        mt1 = fmaxf(mt1, __shfl_xor_sync(FM, mt1, 2));
        const float mn0 = fmaxf(mr0, mt0);
        const float mn1 = fmaxf(mr1, mt1);
        const float a0 = __expf(mr0 - mn0);
        const float a1 = __expf(mr1 - mn1);
        float rs0 = 0.f, rs1 = 0.f;
        #pragma unroll
        for (int nt = 0; nt < 8; nt++) {
            s[nt][0] = __expf(s[nt][0] - mn0); rs0 += s[nt][0];
            s[nt][1] = __expf(s[nt][1] - mn0); rs0 += s[nt][1];
            s[nt][2] = __expf(s[nt][2] - mn1); rs1 += s[nt][2];
            s[nt][3] = __expf(s[nt][3] - mn1); rs1 += s[nt][3];
        }
        rs0 += __shfl_xor_sync(FM, rs0, 1);
        rs0 += __shfl_xor_sync(FM, rs0, 2);
        rs1 += __shfl_xor_sync(FM, rs1, 1);
        rs1 += __shfl_xor_sync(FM, rs1, 2);
        lr0 = lr0 * a0 + rs0; mr0 = mn0;
        lr1 = lr1 * a1 + rs1; mr1 = mn1;
        #pragma unroll
        for (int nt = 0; nt < 8; nt++) {
            o[nt][0] *= a0; o[nt][1] *= a0;
            o[nt][2] *= a1; o[nt][3] *= a1;
        }

        // O += P @ V : P fragments gathered from s-registers via shuffles.
        // P[lq][ks*8+j] lives in lane lq*4+(j>>1), element parity j&1.
        #pragma unroll
        for (int ks = 0; ks < 8; ks++) {
            const float e0 = __shfl_sync(FM, s[ks][0], srcA);
            const float e1 = __shfl_sync(FM, s[ks][1], srcA);
            const float e2 = __shfl_sync(FM, s[ks][2], srcA);
            const float e3 = __shfl_sync(FM, s[ks][3], srcA);
            const float f0 = __shfl_sync(FM, s[ks][0], srcB);
            const float f1 = __shfl_sync(FM, s[ks][1], srcB);
            const float f2 = __shfl_sync(FM, s[ks][2], srcB);
            const float f3 = __shfl_sync(FM, s[ks][3], srcB);
            const float p0 = oddc ? e1 : e0;   // P[lq][ks*8+lr]
            const float p1 = oddc ? e3 : e2;   // P[lq+8][ks*8+lr]
            const float p2 = oddc ? f1 : f0;   // P[lq][ks*8+lr+4]
            const float p3 = oddc ? f3 : f2;   // P[lq+8][ks*8+lr+4]
            uint32_t ph[4], pl[4];
            split_hl_u(p0, ph[0], pl[0]);
            split_hl_u(p1, ph[1], pl[1]);
            split_hl_u(p2, ph[2], pl[2]);
            split_hl_u(p3, ph[3], pl[3]);
            const int k0 = ks * 8;
            #pragma unroll
            for (int nt = 0; nt < 8; nt++) {
                const int cb = (nt * 8 + lq) * FST + k0 + lr;
                uint32_t vh[2], vl[2];
                split_hl_u(Vts[cb],     vh[0], vl[0]);
                split_hl_u(Vts[cb + 4], vh[1], vl[1]);
                mma_tf32(o[nt], ph, vh);
                mma_tf32(o[nt], ph, vl);
                mma_tf32(o[nt], pl, vh);
            }
        }
    }

    // epilogue: normalize, write context
    const float inv0 = 1.0f / lr0;
    const float inv1 = 1.0f / lr1;
    const size_t ro0 = base + (size_t)(qt * 64 + wrow + lq) * Ec;
    const size_t ro1 = base + (size_t)(qt * 64 + wrow + lq + 8) * Ec;
    #pragma unroll
    for (int nt = 0; nt < 8; nt++) {
        const int cc = nt * 8 + lr * 2;
        *(float2*)&Ctx[ro0 + cc] = make_float2(o[nt][0] * inv0, o[nt][1] * inv0);
        *(float2*)&Ctx[ro1 + cc] = make_float2(o[nt][2] * inv1, o[nt][3] * inv1);
    }
}

// ---------------------------------------------------------------------------
extern "C" void kernel_launch(void* const* d_in, const int* in_sizes, int n_in,
                              void* d_out, int out_size) {
    (void)in_sizes; (void)n_in; (void)out_size;
    const float* x  = (const float*)d_in[0];
    const float* wq = (const float*)d_in[1];
    const float* wk = (const float*)d_in[2];
    const float* wv = (const float*)d_in[3];
    const float* wo = (const float*)d_in[4];
    float* out = (float*)d_out;

    float *q, *k, *v, *ctx;
    cudaGetSymbolAddress((void**)&q,   g_q);
    cudaGetSymbolAddress((void**)&k,   g_k);
    cudaGetSymbolAddress((void**)&v,   g_v);
    cudaGetSymbolAddress((void**)&ctx, g_ctx);

    const int gsmem = 2 * 128 * PADS * (int)sizeof(float);   // 36864 B
    cudaFuncSetAttribute(gemm3_mma, cudaFuncAttributeMaxDynamicSharedMemorySize, gsmem);
    const dim3 ggrd(Ec / 128, NTOK / 128);

    gemm3_mma<<<ggrd, 256, gsmem>>>(x, wq, q);
    gemm3_mma<<<ggrd, 256, gsmem>>>(x, wk, k);
    gemm3_mma<<<ggrd, 256, gsmem>>>(x, wv, v);

    cudaFuncSetAttribute(flash_attn_mma, cudaFuncAttributeMaxDynamicSharedMemorySize, FA_SMEM);
    flash_attn_mma<<<dim3(Sc / 64, Hc, Bc), 128, FA_SMEM>>>(q, k, v, ctx);

    gemm3_mma<<<ggrd, 256, gsmem>>>(ctx, wo, out);
}

// round 6
// speedup vs baseline: 2.6056x; 1.5948x over previous
#include <cuda_runtime.h>
#include <cstdint>
#include <math.h>

// Problem constants
#define Bc   2
#define Sc   2048
#define Ec   1024
#define Hc   16
#define Dc   64
#define NTOK (Bc*Sc)          // 4096
#define ATT_SCALE 0.125f

// Scratch (static __device__ — no allocation allowed)
__device__ float g_q  [Bc*Sc*Ec];
__device__ float g_k  [Bc*Sc*Ec];
__device__ float g_v  [Bc*Sc*Ec];
__device__ float g_ctx[Bc*Sc*Ec];

// ---------------------------------------------------------------------------
// bf16 helpers: split fp32 pair into packed bf16x2 (hi = truncate, lo = v-hi)
// lower 16 bits of the bf16x2 reg = first value of the pair.
// ---------------------------------------------------------------------------
__device__ __forceinline__ void split_pack(float v0, float v1, uint32_t& h, uint32_t& l) {
    const uint32_t u0 = __float_as_uint(v0);
    const uint32_t u1 = __float_as_uint(v1);
    uint32_t hp;
    asm("prmt.b32 %0, %1, %2, 0x7632;" : "=r"(hp) : "r"(u0), "r"(u1));
    const float l0 = v0 - __uint_as_float(u0 & 0xFFFF0000u);
    const float l1 = v1 - __uint_as_float(u1 & 0xFFFF0000u);
    uint32_t lp;
    asm("cvt.rn.bf16x2.f32 %0, %1, %2;" : "=r"(lp) : "f"(l1), "f"(l0));  // first src -> upper
    h = hp; l = lp;
}

__device__ __forceinline__ void mma_bf16(float* c, const uint32_t* a, const uint32_t* b) {
    asm volatile(
        "mma.sync.aligned.m16n8k16.row.col.f32.bf16.bf16.f32 "
        "{%0,%1,%2,%3}, {%4,%5,%6,%7}, {%8,%9}, {%0,%1,%2,%3};"
        : "+f"(c[0]), "+f"(c[1]), "+f"(c[2]), "+f"(c[3])
        : "r"(a[0]), "r"(a[1]), "r"(a[2]), "r"(a[3]), "r"(b[0]), "r"(b[1]));
}

// ---------------------------------------------------------------------------
// 3xBF16 GEMM via mma.sync m16n8k16.  C[M,N] = A[M,K] @ W[N,K]^T.
// 128x128 CTA tile, k-panel 32 (16 bf16x2 pairs), 256 thr, 8 warps (2x4).
// Smem holds pre-split packed bf16x2 pairs; pair-row stride 20 (conflict-free).
// ---------------------------------------------------------------------------
#define GK   Ec
#define KPAN 32
#define PRS  20

__global__ void __launch_bounds__(256, 2) gemm3_bf16(const float* __restrict__ A,
                                                     const float* __restrict__ W,
                                                     float* __restrict__ C) {
    extern __shared__ uint32_t smu[];
    uint32_t* Ah = smu;                     // [128][PRS] (16 pairs used)
    uint32_t* Al = Ah + 128 * PRS;
    uint32_t* Bh = Al + 128 * PRS;
    uint32_t* Bl = Bh + 128 * PRS;

    const int tid  = threadIdx.x;
    const int wid  = tid >> 5;
    const int lane = tid & 31;
    const int wm   = (wid & 1) * 64;
    const int wn   = (wid >> 1) * 32;
    const int m0   = blockIdx.y * 128;
    const int n0   = blockIdx.x * 128;

    const int lq = lane >> 2;
    const int lr = lane & 3;

    float acc[4][4][4];
    #pragma unroll
    for (int i = 0; i < 4; i++)
        #pragma unroll
        for (int j = 0; j < 4; j++)
            #pragma unroll
            for (int e = 0; e < 4; e++) acc[i][j][e] = 0.f;

    for (int kk = 0; kk < GK; kk += KPAN) {
        __syncthreads();
        #pragma unroll
        for (int it = 0; it < 4; it++) {
            const int i  = tid + it * 256;
            const int r  = i >> 3;
            const int c4 = (i & 7) * 4;       // k offset (multiple of 4)
            const int p  = c4 >> 1;           // pair index (even)
            float4 va = *(const float4*)&A[(size_t)(m0 + r) * GK + kk + c4];
            float4 vb = *(const float4*)&W[(size_t)(n0 + r) * GK + kk + c4];
            uint32_t h0, l0, h1, l1;
            split_pack(va.x, va.y, h0, l0);
            split_pack(va.z, va.w, h1, l1);
            *(uint2*)&Ah[r * PRS + p] = make_uint2(h0, h1);
            *(uint2*)&Al[r * PRS + p] = make_uint2(l0, l1);
            split_pack(vb.x, vb.y, h0, l0);
            split_pack(vb.z, vb.w, h1, l1);
            *(uint2*)&Bh[r * PRS + p] = make_uint2(h0, h1);
            *(uint2*)&Bl[r * PRS + p] = make_uint2(l0, l1);
        }
        __syncthreads();

        #pragma unroll
        for (int s2 = 0; s2 < 2; s2++) {      // two K=16 steps per panel
            const int pb = s2 * 8;
            uint32_t ah[4][4], al[4][4];
            #pragma unroll
            for (int mt = 0; mt < 4; mt++) {
                const int b0 = (wm + mt * 16 + lq) * PRS + pb + lr;
                const int b1 = b0 + 8 * PRS;
                ah[mt][0] = Ah[b0]; ah[mt][1] = Ah[b1];
                ah[mt][2] = Ah[b0 + 4]; ah[mt][3] = Ah[b1 + 4];
                al[mt][0] = Al[b0]; al[mt][1] = Al[b1];
                al[mt][2] = Al[b0 + 4]; al[mt][3] = Al[b1 + 4];
            }
            #pragma unroll
            for (int nt = 0; nt < 4; nt++) {
                const int bb = (wn + nt * 8 + lq) * PRS + pb + lr;
                uint32_t bh[2], bl[2];
                bh[0] = Bh[bb]; bh[1] = Bh[bb + 4];
                bl[0] = Bl[bb]; bl[1] = Bl[bb + 4];
                #pragma unroll
                for (int mt = 0; mt < 4; mt++) {
                    mma_bf16(acc[mt][nt], ah[mt], bh);
                    mma_bf16(acc[mt][nt], ah[mt], bl);
                    mma_bf16(acc[mt][nt], al[mt], bh);
                }
            }
        }
    }

    #pragma unroll
    for (int mt = 0; mt < 4; mt++) {
        const int r0 = m0 + wm + mt * 16 + lq;
        #pragma unroll
        for (int nt = 0; nt < 4; nt++) {
            const int cc = n0 + wn + nt * 8 + lr * 2;
            *(float2*)&C[(size_t)r0 * Ec + cc]       = make_float2(acc[mt][nt][0], acc[mt][nt][1]);
            *(float2*)&C[(size_t)(r0 + 8) * Ec + cc] = make_float2(acc[mt][nt][2], acc[mt][nt][3]);
        }
    }
}
#define GEMM_SMEM (4 * 128 * PRS * 4)   // 40960 B

// ---------------------------------------------------------------------------
// Flash attention, causal, 3xBF16 m16n8k16.
// CTA = 64 q-rows, kv tiles of 64, 4 warps (warp = 16 rows x 64 cols).
// Smem: packed bf16x2 pairs, pair-row stride 36 (conflict-free).
//   Qh/Ql [64 rows][32 dim-pairs], Kh/Kl same, Vth/Vtl [64 dims][32 key-pairs]
// P fragments come straight from S registers (layout identity) — no smem/shfl.
// ---------------------------------------------------------------------------
#define PST 36
#define FA_SMEM (6 * 64 * PST * 4)   // 55296 B -> 4 CTAs/SM

__global__ void __launch_bounds__(128, 4) flash_attn_mma(const float* __restrict__ Q,
                                                         const float* __restrict__ Kg,
                                                         const float* __restrict__ Vg,
                                                         float* __restrict__ Ctx) {
    extern __shared__ uint32_t smu[];
    uint32_t* Qh  = smu;
    uint32_t* Ql  = Qh  + 64 * PST;
    uint32_t* Kh  = Ql  + 64 * PST;
    uint32_t* Kl  = Kh  + 64 * PST;
    uint32_t* Vth = Kl  + 64 * PST;   // [dim][key-pair]
    uint32_t* Vtl = Vth + 64 * PST;

    const int tid  = threadIdx.x;
    const int wid  = tid >> 5;
    const int lane = tid & 31;
    const int lq   = lane >> 2;
    const int lr   = lane & 3;
    const int wrow = wid * 16;

    const int qt = gridDim.x - 1 - blockIdx.x;   // long CTAs first
    const int h  = blockIdx.y;
    const int b  = blockIdx.z;
    const size_t base = (size_t)b * Sc * Ec + (size_t)h * Dc;

    // stage Q (split+packed)
    #pragma unroll
    for (int it = 0; it < 8; it++) {
        const int i  = tid + it * 128;
        const int r  = i >> 4;
        const int d0 = (i & 15) * 4;
        float4 v = *(const float4*)&Q[base + (size_t)(qt * 64 + r) * Ec + d0];
        uint32_t h0, l0, h1, l1;
        split_pack(v.x, v.y, h0, l0);
        split_pack(v.z, v.w, h1, l1);
        *(uint2*)&Qh[r * PST + (d0 >> 1)] = make_uint2(h0, h1);
        *(uint2*)&Ql[r * PST + (d0 >> 1)] = make_uint2(l0, l1);
    }

    float o[8][4];
    #pragma unroll
    for (int nt = 0; nt < 8; nt++)
        #pragma unroll
        for (int e = 0; e < 4; e++) o[nt][e] = 0.f;
    float mr0 = -1e30f, mr1 = -1e30f, lr0 = 0.f, lr1 = 0.f;

    const unsigned FM = 0xffffffffu;

    for (int jt = 0; jt <= qt; jt++) {
        __syncthreads();  // previous iter done reading Ks/Vts
        // stage K rowwise (dim pairs)
        #pragma unroll
        for (int it = 0; it < 8; it++) {
            const int i  = tid + it * 128;
            const int r  = i >> 4;
            const int d0 = (i & 15) * 4;
            float4 v = *(const float4*)&Kg[base + (size_t)(jt * 64 + r) * Ec + d0];
            uint32_t h0, l0, h1, l1;
            split_pack(v.x, v.y, h0, l0);
            split_pack(v.z, v.w, h1, l1);
            *(uint2*)&Kh[r * PST + (d0 >> 1)] = make_uint2(h0, h1);
            *(uint2*)&Kl[r * PST + (d0 >> 1)] = make_uint2(l0, l1);
        }
        // stage V transposed (key pairs)
        #pragma unroll
        for (int it = 0; it < 4; it++) {
            const int i  = tid + it * 128;
            const int kp = i >> 4;            // key pair 0..31
            const int d0 = (i & 15) * 4;
            const size_t g = base + (size_t)(jt * 64 + kp * 2) * Ec + d0;
            float4 v0 = *(const float4*)&Vg[g];
            float4 v1 = *(const float4*)&Vg[g + Ec];
            uint32_t hh, ll;
            split_pack(v0.x, v1.x, hh, ll); Vth[(d0+0)*PST + kp] = hh; Vtl[(d0+0)*PST + kp] = ll;
            split_pack(v0.y, v1.y, hh, ll); Vth[(d0+1)*PST + kp] = hh; Vtl[(d0+1)*PST + kp] = ll;
            split_pack(v0.z, v1.z, hh, ll); Vth[(d0+2)*PST + kp] = hh; Vtl[(d0+2)*PST + kp] = ll;
            split_pack(v0.w, v1.w, hh, ll); Vth[(d0+3)*PST + kp] = hh; Vtl[(d0+3)*PST + kp] = ll;
        }
        __syncthreads();

        // S = Q @ K^T  (3xBF16, K=64 in 4 chunks of 16)
        float s[8][4];
        #pragma unroll
        for (int nt = 0; nt < 8; nt++)
            #pragma unroll
            for (int e = 0; e < 4; e++) s[nt][e] = 0.f;

        #pragma unroll
        for (int ks = 0; ks < 4; ks++) {
            const int pb = ks * 8;
            const int b0 = (wrow + lq) * PST + pb + lr;
            const int b1 = b0 + 8 * PST;
            uint32_t ah[4], al[4];
            ah[0] = Qh[b0]; ah[1] = Qh[b1]; ah[2] = Qh[b0 + 4]; ah[3] = Qh[b1 + 4];
            al[0] = Ql[b0]; al[1] = Ql[b1]; al[2] = Ql[b0 + 4]; al[3] = Ql[b1 + 4];
            #pragma unroll
            for (int nt = 0; nt < 8; nt++) {
                const int kb = (nt * 8 + lq) * PST + pb + lr;
                uint32_t bh[2], bl[2];
                bh[0] = Kh[kb]; bh[1] = Kh[kb + 4];
                bl[0] = Kl[kb]; bl[1] = Kl[kb + 4];
                mma_bf16(s[nt], ah, bh);
                mma_bf16(s[nt], ah, bl);
                mma_bf16(s[nt], al, bh);
            }
        }

        // scale + causal mask on diagonal tile
        if (jt == qt) {
            const int row0 = wrow + lq, row1 = wrow + lq + 8;
            #pragma unroll
            for (int nt = 0; nt < 8; nt++) {
                const int c0 = nt * 8 + lr * 2;
                s[nt][0] = (c0     > row0) ? -1e30f : s[nt][0] * ATT_SCALE;
                s[nt][1] = (c0 + 1 > row0) ? -1e30f : s[nt][1] * ATT_SCALE;
                s[nt][2] = (c0     > row1) ? -1e30f : s[nt][2] * ATT_SCALE;
                s[nt][3] = (c0 + 1 > row1) ? -1e30f : s[nt][3] * ATT_SCALE;
            }
        } else {
            #pragma unroll
            for (int nt = 0; nt < 8; nt++)
                #pragma unroll
                for (int e = 0; e < 4; e++) s[nt][e] *= ATT_SCALE;
        }

        // online softmax (rows lq, lq+8; reduce across lanes sharing lq)
        float mt0 = -1e30f, mt1 = -1e30f;
        #pragma unroll
        for (int nt = 0; nt < 8; nt++) {
            mt0 = fmaxf(mt0, fmaxf(s[nt][0], s[nt][1]));
            mt1 = fmaxf(mt1, fmaxf(s[nt][2], s[nt][3]));
        }
        mt0 = fmaxf(mt0, __shfl_xor_sync(FM, mt0, 1));
        mt0 = fmaxf(mt0, __shfl_xor_sync(FM, mt0, 2));
        mt1 = fmaxf(mt1, __shfl_xor_sync(FM, mt1, 1));
        mt1 = fmaxf(mt1, __shfl_xor_sync(FM, mt1, 2));
        const float mn0 = fmaxf(mr0, mt0);
        const float mn1 = fmaxf(mr1, mt1);
        const float a0 = __expf(mr0 - mn0);
        const float a1 = __expf(mr1 - mn1);
        float rs0 = 0.f, rs1 = 0.f;
        #pragma unroll
        for (int nt = 0; nt < 8; nt++) {
            s[nt][0] = __expf(s[nt][0] - mn0); rs0 += s[nt][0];
            s[nt][1] = __expf(s[nt][1] - mn0); rs0 += s[nt][1];
            s[nt][2] = __expf(s[nt][2] - mn1); rs1 += s[nt][2];
            s[nt][3] = __expf(s[nt][3] - mn1); rs1 += s[nt][3];
        }
        rs0 += __shfl_xor_sync(FM, rs0, 1);
        rs0 += __shfl_xor_sync(FM, rs0, 2);
        rs1 += __shfl_xor_sync(FM, rs1, 1);
        rs1 += __shfl_xor_sync(FM, rs1, 2);
        lr0 = lr0 * a0 + rs0; mr0 = mn0;
        lr1 = lr1 * a1 + rs1; mr1 = mn1;
        #pragma unroll
        for (int nt = 0; nt < 8; nt++) {
            o[nt][0] *= a0; o[nt][1] *= a0;
            o[nt][2] *= a1; o[nt][3] *= a1;
        }

        // O += P @ V : P A-fragments are this lane's own S registers.
        #pragma unroll
        for (int ks = 0; ks < 4; ks++) {
            uint32_t ph[4], pl[4];
            split_pack(s[2*ks][0],   s[2*ks][1],   ph[0], pl[0]);
            split_pack(s[2*ks][2],   s[2*ks][3],   ph[1], pl[1]);
            split_pack(s[2*ks+1][0], s[2*ks+1][1], ph[2], pl[2]);
            split_pack(s[2*ks+1][2], s[2*ks+1][3], ph[3], pl[3]);
            const int pb = ks * 8;
            #pragma unroll
            for (int nt = 0; nt < 8; nt++) {
                const int vb = (nt * 8 + lq) * PST + pb + lr;
                uint32_t vh[2], vl[2];
                vh[0] = Vth[vb]; vh[1] = Vth[vb + 4];
                vl[0] = Vtl[vb]; vl[1] = Vtl[vb + 4];
                mma_bf16(o[nt], ph, vh);
                mma_bf16(o[nt], ph, vl);
                mma_bf16(o[nt], pl, vh);
            }
        }
    }

    // epilogue: normalize, write context
    const float inv0 = 1.0f / lr0;
    const float inv1 = 1.0f / lr1;
    const size_t ro0 = base + (size_t)(qt * 64 + wrow + lq) * Ec;
    const size_t ro1 = base + (size_t)(qt * 64 + wrow + lq + 8) * Ec;
    #pragma unroll
    for (int nt = 0; nt < 8; nt++) {
        const int cc = nt * 8 + lr * 2;
        *(float2*)&Ctx[ro0 + cc] = make_float2(o[nt][0] * inv0, o[nt][1] * inv0);
        *(float2*)&Ctx[ro1 + cc] = make_float2(o[nt][2] * inv1, o[nt][3] * inv1);
    }
}

// ---------------------------------------------------------------------------
extern "C" void kernel_launch(void* const* d_in, const int* in_sizes, int n_in,
                              void* d_out, int out_size) {
    (void)in_sizes; (void)n_in; (void)out_size;
    const float* x  = (const float*)d_in[0];
    const float* wq = (const float*)d_in[1];
    const float* wk = (const float*)d_in[2];
    const float* wv = (const float*)d_in[3];
    const float* wo = (const float*)d_in[4];
    float* out = (float*)d_out;

    float *q, *k, *v, *ctx;
    cudaGetSymbolAddress((void**)&q,   g_q);
    cudaGetSymbolAddress((void**)&k,   g_k);
    cudaGetSymbolAddress((void**)&v,   g_v);
    cudaGetSymbolAddress((void**)&ctx, g_ctx);

    cudaFuncSetAttribute(gemm3_bf16, cudaFuncAttributeMaxDynamicSharedMemorySize, GEMM_SMEM);
    const dim3 ggrd(Ec / 128, NTOK / 128);

    gemm3_bf16<<<ggrd, 256, GEMM_SMEM>>>(x, wq, q);
    gemm3_bf16<<<ggrd, 256, GEMM_SMEM>>>(x, wk, k);
    gemm3_bf16<<<ggrd, 256, GEMM_SMEM>>>(x, wv, v);

    cudaFuncSetAttribute(flash_attn_mma, cudaFuncAttributeMaxDynamicSharedMemorySize, FA_SMEM);
    flash_attn_mma<<<dim3(Sc / 64, Hc, Bc), 128, FA_SMEM>>>(q, k, v, ctx);

    gemm3_bf16<<<ggrd, 256, GEMM_SMEM>>>(ctx, wo, out);
}